// round 3
// baseline (speedup 1.0000x reference)
#include <cuda_runtime.h>

#define BB 16
#define NN 1024
#define FF 256
#define NT 16384
#define EE 524288
#define CONN 16777216
#define LOG_EPS -23.025850929940457f

// ---- scratch (device globals: allocation-free) ----
__device__ int   g_is64;
__device__ int   g_src[EE];
__device__ int   g_dst[EE];
__device__ float g_param[BB];
__device__ float g_h0[NT];
__device__ float g_agg1[NT];
__device__ float g_deg[NT];
__device__ float g_h1[NT * 8];
__device__ float g_agg2[NT * 8];
__device__ float g_out[NT * 16];
__device__ float g_adj[CONN];   // touched entries only; restored to 0 each launch

__device__ __forceinline__ float leaky(float v) { return v >= 0.f ? v : 0.01f * v; }
__device__ __forceinline__ float sigf(float t) {
    return __fdividef(1.f, 1.f + __expf(-t));
}
__device__ __forceinline__ float wred(float v) {
#pragma unroll
    for (int o = 16; o; o >>= 1) v += __shfl_down_sync(0xffffffffu, v, o);
    return v;
}

// Detect whether edge_index is stored as int64 (odd int32 words = high halves = 0)
// or as int32 (odd words are random node ids in [0,16384), OR != 0 w.o.p.).
__global__ void k_detect(const int* __restrict__ ei32) {
    int lane = threadIdx.x;
    unsigned v = 0;
    for (int i = 1 + 2 * lane; i < 1024; i += 64) v |= (unsigned)ei32[i];
    unsigned any = __ballot_sync(0xffffffffu, v != 0u);
    if (lane == 0) g_is64 = (any == 0u) ? 1 : 0;
}

// Materialize int32 src/dst regardless of input width.
__global__ void k_cvt(const int* __restrict__ ei32) {
    int e = blockIdx.x * blockDim.x + threadIdx.x;
    if (g_is64) {
        g_src[e] = ei32[2 * e];
        g_dst[e] = ei32[2 * (EE + e)];
    } else {
        g_src[e] = ei32[e];
        g_dst[e] = ei32[EE + e];
    }
}

// zero the small per-launch accumulators (adj handled by sparse restore)
__global__ void k_zero() {
    int i = blockIdx.x * blockDim.x + threadIdx.x;
    if (i < NT) { g_agg1[i] = 0.f; g_deg[i] = 0.f; }
    if (i < NT * 8) g_agg2[i] = 0.f;
}

// param[b] = relu(x[b,:] . W11 + b11); optionally writes param to output tail
__global__ void k_param(const float* __restrict__ x, const float* __restrict__ W11,
                        const float* __restrict__ b11, float* __restrict__ outp,
                        int write_out) {
    int w = threadIdx.x >> 5, lane = threadIdx.x & 31;
    float s = 0.f;
    for (int f = lane; f < FF; f += 32) s += x[w * FF + f] * W11[f];
    s = wred(s);
    if (lane == 0) {
        float p = fmaxf(s + b11[0], 0.f);
        g_param[w] = p;
        if (write_out) outp[w] = p;
    }
}

// h0[b*N+n] = leaky(x[b,:] . W21[n,:] + b21[n])
__global__ void k_h0(const float* __restrict__ x, const float* __restrict__ W21,
                     const float* __restrict__ b21) {
    __shared__ float ws[FF];
    int n = blockIdx.x;
    ws[threadIdx.x] = W21[n * FF + threadIdx.x];
    __syncthreads();
    int w = threadIdx.x >> 5, lane = threadIdx.x & 31;
    float bn = b21[n];
#pragma unroll
    for (int rep = 0; rep < 2; rep++) {
        int b = w + rep * 8;
        float s = 0.f;
        for (int f = lane; f < FF; f += 32) s += x[b * FF + f] * ws[f];
        s = wred(s);
        if (lane == 0) g_h0[b * NN + n] = leaky(s + bn);
    }
}

// layer-1 edge aggregation + degree + sparse adj accumulation
__global__ void k_edge1(const float* __restrict__ ea) {
    int e = blockIdx.x * blockDim.x + threadIdx.x;
    int s = g_src[e], d = g_dst[e];
    float w = ea[e];
    atomicAdd(&g_agg1[d], w * g_h0[s]);
    atomicAdd(&g_deg[d], 1.f);
    atomicAdd(&g_adj[(s << 10) + (d & 1023)], w);   // (b<<20 | n<<10 | m)
}

// h1[i,c] = leaky( (agg1/deg)*Wrel1[c] + brel1[c] + h0[i]*Wroot1[c] )
__global__ void k_h1(const float* __restrict__ Wr, const float* __restrict__ br,
                     const float* __restrict__ Wo) {
    int i = blockIdx.x * blockDim.x + threadIdx.x;
    float a = g_agg1[i] / fmaxf(g_deg[i], 1.f);
    float h = g_h0[i];
    float v[8];
#pragma unroll
    for (int c = 0; c < 8; c++) v[c] = leaky(a * Wr[c] + br[c] + h * Wo[c]);
    float4* o = (float4*)&g_h1[i * 8];
    o[0] = make_float4(v[0], v[1], v[2], v[3]);
    o[1] = make_float4(v[4], v[5], v[6], v[7]);
}

// layer-2 edge aggregation, 8 channels via two vector REDs
__global__ void k_edge2(const float* __restrict__ ea) {
    int e = blockIdx.x * blockDim.x + threadIdx.x;
    int s = g_src[e], d = g_dst[e];
    float w = ea[e];
    const float4* h = (const float4*)&g_h1[s * 8];
    float4 a = h[0], b = h[1];
    float* dst = &g_agg2[d * 8];
    asm volatile("red.global.add.v4.f32 [%0], {%1,%2,%3,%4};" ::"l"(dst),
                 "f"(w * a.x), "f"(w * a.y), "f"(w * a.z), "f"(w * a.w)
                 : "memory");
    asm volatile("red.global.add.v4.f32 [%0], {%1,%2,%3,%4};" ::"l"(dst + 4),
                 "f"(w * b.x), "f"(w * b.y), "f"(w * b.z), "f"(w * b.w)
                 : "memory");
}

// out[i,k] = leaky( (agg2/deg) . Wrel2[k,:] + brel2[k] + h1[i,:] . Wroot2[k,:] )
__global__ void k_out(const float* __restrict__ Wr, const float* __restrict__ br,
                      const float* __restrict__ Wo) {
    __shared__ float sW[128], sR[128], sb[16];
    int t = threadIdx.x;
    if (t < 128) { sW[t] = Wr[t]; sR[t] = Wo[t]; }
    if (t < 16) sb[t] = br[t];
    __syncthreads();
    int i = blockIdx.x * blockDim.x + t;
    float dinv = __fdividef(1.f, fmaxf(g_deg[i], 1.f));
    const float4* ap = (const float4*)&g_agg2[i * 8];
    const float4* hp = (const float4*)&g_h1[i * 8];
    float4 a0 = ap[0], a1 = ap[1], h0v = hp[0], h1v = hp[1];
    float a[8] = {a0.x * dinv, a0.y * dinv, a0.z * dinv, a0.w * dinv,
                  a1.x * dinv, a1.y * dinv, a1.z * dinv, a1.w * dinv};
    float h[8] = {h0v.x, h0v.y, h0v.z, h0v.w, h1v.x, h1v.y, h1v.z, h1v.w};
    float v[16];
#pragma unroll
    for (int k = 0; k < 16; k++) {
        float s = sb[k];
#pragma unroll
        for (int c = 0; c < 8; c++) s += a[c] * sW[k * 8 + c] + h[c] * sR[k * 8 + c];
        v[k] = leaky(s);
    }
    float4* o = (float4*)&g_out[i * 16];
#pragma unroll
    for (int q = 0; q < 4; q++)
        o[q] = make_float4(v[q * 4], v[q * 4 + 1], v[q * 4 + 2], v[q * 4 + 3]);
}

// conn[b,n,m] = sigmoid( out_b[n,:].out_b[m,:] + param[b]*log(1e-10) ) assuming adj=0
__global__ void k_conn(float* __restrict__ out) {
    __shared__ float As[16][132];
    __shared__ float Bs[16][132];
    int b = blockIdx.z;
    int R0 = blockIdx.y << 7, C0 = blockIdx.x << 7;
    const float* ob = g_out + b * NN * 16;
    int tid = threadIdx.x;
#pragma unroll
    for (int it = 0; it < 2; it++) {
        int v = tid + it * 256;           // 512 float4s cover both 128x16 tiles
        int r = v >> 2, q = (v & 3) << 2;
        float4 a = *(const float4*)(ob + (R0 + r) * 16 + q);
        As[q + 0][r] = a.x; As[q + 1][r] = a.y; As[q + 2][r] = a.z; As[q + 3][r] = a.w;
        float4 c = *(const float4*)(ob + (C0 + r) * 16 + q);
        Bs[q + 0][r] = c.x; Bs[q + 1][r] = c.y; Bs[q + 2][r] = c.z; Bs[q + 3][r] = c.w;
    }
    __syncthreads();
    int tx = tid & 15, ty = tid >> 4;
    float acc[8][8];
#pragma unroll
    for (int i = 0; i < 8; i++)
#pragma unroll
        for (int j = 0; j < 8; j++) acc[i][j] = 0.f;
#pragma unroll
    for (int k = 0; k < 16; k++) {
        float4 a0 = *(const float4*)&As[k][ty * 8];
        float4 a1 = *(const float4*)&As[k][ty * 8 + 4];
        float4 c0 = *(const float4*)&Bs[k][tx * 8];
        float4 c1 = *(const float4*)&Bs[k][tx * 8 + 4];
        float av[8] = {a0.x, a0.y, a0.z, a0.w, a1.x, a1.y, a1.z, a1.w};
        float cv[8] = {c0.x, c0.y, c0.z, c0.w, c1.x, c1.y, c1.z, c1.w};
#pragma unroll
        for (int i = 0; i < 8; i++)
#pragma unroll
            for (int j = 0; j < 8; j++) acc[i][j] += av[i] * cv[j];
    }
    float cb = g_param[b] * LOG_EPS;
#pragma unroll
    for (int i = 0; i < 8; i++) {
        int r = R0 + ty * 8 + i;
        float* orow = out + (b << 20) + (r << 10) + C0 + tx * 8;
        float4 v0, v1;
        v0.x = sigf(acc[i][0] + cb); v0.y = sigf(acc[i][1] + cb);
        v0.z = sigf(acc[i][2] + cb); v0.w = sigf(acc[i][3] + cb);
        v1.x = sigf(acc[i][4] + cb); v1.y = sigf(acc[i][5] + cb);
        v1.z = sigf(acc[i][6] + cb); v1.w = sigf(acc[i][7] + cb);
        *(float4*)orow = v0;
        *(float4*)(orow + 4) = v1;
    }
}

// fix up the (sparse) entries where adj != 0; idempotent under duplicate edges
__global__ void k_fix(float* __restrict__ out) {
    int e = blockIdx.x * blockDim.x + threadIdx.x;
    int s = g_src[e], d = g_dst[e];
    int idx = (s << 10) + (d & 1023);
    float adjv = g_adj[idx];
    const float4* A = (const float4*)&g_out[s * 16];
    const float4* C = (const float4*)&g_out[d * 16];
    float g = 0.f;
#pragma unroll
    for (int q = 0; q < 4; q++) {
        float4 a = A[q], c = C[q];
        g += a.x * c.x + a.y * c.y + a.z * c.z + a.w * c.w;
    }
    float p = g_param[s >> 10];
    out[idx] = sigf(g + logf(adjv + 1e-10f) * p);
}

// restore touched adj entries to zero so graph replay stays deterministic
__global__ void k_restore() {
    int e = blockIdx.x * blockDim.x + threadIdx.x;
    g_adj[(g_src[e] << 10) + (g_dst[e] & 1023)] = 0.f;
}

extern "C" void kernel_launch(void* const* d_in, const int* in_sizes, int n_in,
                              void* d_out, int out_size) {
    const float* x      = (const float*)d_in[0];
    const int*   ei32   = (const int*)d_in[1];   // width auto-detected
    const float* ea     = (const float*)d_in[2];
    // d_in[3] = batch (unused; graph id derivable from node id)
    const float* W11    = (const float*)d_in[4];
    const float* b11    = (const float*)d_in[5];
    const float* W21    = (const float*)d_in[6];
    const float* b21    = (const float*)d_in[7];
    const float* Wrel1  = (const float*)d_in[8];
    const float* brel1  = (const float*)d_in[9];
    const float* Wroot1 = (const float*)d_in[10];
    const float* Wrel2  = (const float*)d_in[11];
    const float* brel2  = (const float*)d_in[12];
    const float* Wroot2 = (const float*)d_in[13];
    float* out = (float*)d_out;

    int write_param = (out_size >= CONN + BB) ? 1 : 0;

    k_detect<<<1, 32>>>(ei32);
    k_cvt<<<EE / 256, 256>>>(ei32);
    k_zero<<<128, 1024>>>();
    k_param<<<1, 512>>>(x, W11, b11, out + CONN, write_param);
    k_h0<<<1024, 256>>>(x, W21, b21);
    k_edge1<<<EE / 256, 256>>>(ea);
    k_h1<<<NT / 256, 256>>>(Wrel1, brel1, Wroot1);
    k_edge2<<<EE / 256, 256>>>(ea);
    k_out<<<NT / 128, 128>>>(Wrel2, brel2, Wroot2);
    k_conn<<<dim3(8, 8, 16), 256>>>(out);
    k_fix<<<EE / 256, 256>>>(out);
    k_restore<<<EE / 256, 256>>>();
}

// round 4
// speedup vs baseline: 1.0952x; 1.0952x over previous
#include <cuda_runtime.h>

#define BB 16
#define NN 1024
#define FF 256
#define NT 16384
#define EE 524288
#define CONN 16777216
#define LOG_EPS -23.025850929940457f

// ---- scratch (device globals: allocation-free; zero-init at load, every
// ---- launch leaves them zeroed again so graph replays are deterministic) ----
__device__ int2  g_edge[EE];
__device__ float g_param[BB];
__device__ float g_h0[NT];
__device__ float g_agg1[NT];   // zeroed by k_h1 after consumption
__device__ float g_deg[NT];    // zeroed by k_out after consumption
__device__ float g_h1[NT * 8];
__device__ float g_agg2[NT * 8]; // zeroed by k_out after consumption
__device__ float g_out[NT * 16];
__device__ float g_adj[CONN];  // touched entries zeroed by atomicExch in k_fixres

__device__ __forceinline__ float leaky(float v) { return v >= 0.f ? v : 0.01f * v; }
__device__ __forceinline__ float sigf(float t) {
    return __fdividef(1.f, 1.f + __expf(-t));
}
__device__ __forceinline__ float wred(float v) {
#pragma unroll
    for (int o = 16; o; o >>= 1) v += __shfl_down_sync(0xffffffffu, v, o);
    return v;
}

// Convert edge_index (width auto-detected per-thread from one broadcast line)
// into packed int2 (src, dst).
__global__ void k_cvt(const int* __restrict__ ei32) {
    int e = blockIdx.x * blockDim.x + threadIdx.x;
    // int64 => odd words of the first 8 values are high halves == 0.
    // int32 => odd words are random node ids in [0,16384); all-zero w.p. 2^-112.
    unsigned probe = (unsigned)ei32[1] | (unsigned)ei32[3] | (unsigned)ei32[5] |
                     (unsigned)ei32[7] | (unsigned)ei32[9] | (unsigned)ei32[11] |
                     (unsigned)ei32[13] | (unsigned)ei32[15];
    int s, d;
    if (probe == 0u) {                 // int64 storage
        s = ei32[2 * e];
        d = ei32[2 * (EE + e)];
    } else {                           // int32 storage
        s = ei32[e];
        d = ei32[EE + e];
    }
    g_edge[e] = make_int2(s, d);
}

// blocks 0..1023: h0[b*N+n] = leaky(x[b,:] . W21[n,:] + b21[n])
// block 1024:     param[b]  = relu(x[b,:] . W11 + b11)
__global__ void k_h0(const float* __restrict__ x, const float* __restrict__ W21,
                     const float* __restrict__ b21, const float* __restrict__ W11,
                     const float* __restrict__ b11, float* __restrict__ outp,
                     int write_param) {
    int w = threadIdx.x >> 5, lane = threadIdx.x & 31;
    if (blockIdx.x == NN) {            // param block
#pragma unroll
        for (int rep = 0; rep < 2; rep++) {
            int b = w + rep * 8;
            float s = 0.f;
            for (int f = lane; f < FF; f += 32) s += x[b * FF + f] * W11[f];
            s = wred(s);
            if (lane == 0) {
                float p = fmaxf(s + b11[0], 0.f);
                g_param[b] = p;
                if (write_param) outp[b] = p;
            }
        }
        return;
    }
    __shared__ float ws[FF];
    int n = blockIdx.x;
    ws[threadIdx.x] = W21[n * FF + threadIdx.x];
    __syncthreads();
    float bn = b21[n];
#pragma unroll
    for (int rep = 0; rep < 2; rep++) {
        int b = w + rep * 8;
        float s = 0.f;
        for (int f = lane; f < FF; f += 32) s += x[b * FF + f] * ws[f];
        s = wred(s);
        if (lane == 0) g_h0[b * NN + n] = leaky(s + bn);
    }
}

// layer-1 edge aggregation + degree + sparse adj accumulation
__global__ void k_edge1(const float* __restrict__ ea) {
    int e = blockIdx.x * blockDim.x + threadIdx.x;
    int2 sd = g_edge[e];
    float w = ea[e];
    atomicAdd(&g_agg1[sd.y], w * g_h0[sd.x]);
    atomicAdd(&g_deg[sd.y], 1.f);
    atomicAdd(&g_adj[(sd.x << 10) + (sd.y & 1023)], w);  // (b<<20 | n<<10 | m)
}

// h1[i,c] = leaky( (agg1/deg)*Wrel1[c] + brel1[c] + h0[i]*Wroot1[c] ); zero agg1
__global__ void k_h1(const float* __restrict__ Wr, const float* __restrict__ br,
                     const float* __restrict__ Wo) {
    int i = blockIdx.x * blockDim.x + threadIdx.x;
    float a = g_agg1[i] / fmaxf(g_deg[i], 1.f);
    g_agg1[i] = 0.f;                   // restore for next replay
    float h = g_h0[i];
    float v[8];
#pragma unroll
    for (int c = 0; c < 8; c++) v[c] = leaky(a * Wr[c] + br[c] + h * Wo[c]);
    float4* o = (float4*)&g_h1[i * 8];
    o[0] = make_float4(v[0], v[1], v[2], v[3]);
    o[1] = make_float4(v[4], v[5], v[6], v[7]);
}

// layer-2 edge aggregation, 8 channels via two vector REDs
__global__ void k_edge2(const float* __restrict__ ea) {
    int e = blockIdx.x * blockDim.x + threadIdx.x;
    int2 sd = g_edge[e];
    float w = ea[e];
    const float4* h = (const float4*)&g_h1[sd.x * 8];
    float4 a = h[0], b = h[1];
    float* dst = &g_agg2[sd.y * 8];
    asm volatile("red.global.add.v4.f32 [%0], {%1,%2,%3,%4};" ::"l"(dst),
                 "f"(w * a.x), "f"(w * a.y), "f"(w * a.z), "f"(w * a.w)
                 : "memory");
    asm volatile("red.global.add.v4.f32 [%0], {%1,%2,%3,%4};" ::"l"(dst + 4),
                 "f"(w * b.x), "f"(w * b.y), "f"(w * b.z), "f"(w * b.w)
                 : "memory");
}

// out[i,k] = leaky( (agg2/deg) . Wrel2[k,:] + brel2[k] + h1[i,:] . Wroot2[k,:] )
// zeroes agg2 and deg afterward
__global__ void k_out(const float* __restrict__ Wr, const float* __restrict__ br,
                      const float* __restrict__ Wo) {
    __shared__ float sW[128], sR[128], sb[16];
    int t = threadIdx.x;
    if (t < 128) { sW[t] = Wr[t]; sR[t] = Wo[t]; }
    if (t < 16) sb[t] = br[t];
    __syncthreads();
    int i = blockIdx.x * blockDim.x + t;
    float dinv = __fdividef(1.f, fmaxf(g_deg[i], 1.f));
    g_deg[i] = 0.f;                    // restore
    float4* ap = (float4*)&g_agg2[i * 8];
    const float4* hp = (const float4*)&g_h1[i * 8];
    float4 a0 = ap[0], a1 = ap[1], h0v = hp[0], h1v = hp[1];
    ap[0] = make_float4(0.f, 0.f, 0.f, 0.f);   // restore
    ap[1] = make_float4(0.f, 0.f, 0.f, 0.f);
    float a[8] = {a0.x * dinv, a0.y * dinv, a0.z * dinv, a0.w * dinv,
                  a1.x * dinv, a1.y * dinv, a1.z * dinv, a1.w * dinv};
    float h[8] = {h0v.x, h0v.y, h0v.z, h0v.w, h1v.x, h1v.y, h1v.z, h1v.w};
    float v[16];
#pragma unroll
    for (int k = 0; k < 16; k++) {
        float s = sb[k];
#pragma unroll
        for (int c = 0; c < 8; c++) s += a[c] * sW[k * 8 + c] + h[c] * sR[k * 8 + c];
        v[k] = leaky(s);
    }
    float4* o = (float4*)&g_out[i * 16];
#pragma unroll
    for (int q = 0; q < 4; q++)
        o[q] = make_float4(v[q * 4], v[q * 4 + 1], v[q * 4 + 2], v[q * 4 + 3]);
}

// conn[b,n,m] = sigmoid( out_b[n,:].out_b[m,:] + param[b]*log(1e-10) ) assuming adj=0
__global__ void k_conn(float* __restrict__ out) {
    __shared__ float As[16][132];
    __shared__ float Bs[16][132];
    int b = blockIdx.z;
    int R0 = blockIdx.y << 7, C0 = blockIdx.x << 7;
    const float* ob = g_out + b * NN * 16;
    int tid = threadIdx.x;
#pragma unroll
    for (int it = 0; it < 2; it++) {
        int v = tid + it * 256;            // 512 float4s cover both 128x16 tiles
        int r = v >> 2, q = (v & 3) << 2;
        float4 a = *(const float4*)(ob + (R0 + r) * 16 + q);
        As[q + 0][r] = a.x; As[q + 1][r] = a.y; As[q + 2][r] = a.z; As[q + 3][r] = a.w;
        float4 c = *(const float4*)(ob + (C0 + r) * 16 + q);
        Bs[q + 0][r] = c.x; Bs[q + 1][r] = c.y; Bs[q + 2][r] = c.z; Bs[q + 3][r] = c.w;
    }
    __syncthreads();
    int tx = tid & 15, ty = tid >> 4;
    float acc[8][8];
#pragma unroll
    for (int i = 0; i < 8; i++)
#pragma unroll
        for (int j = 0; j < 8; j++) acc[i][j] = 0.f;
#pragma unroll
    for (int k = 0; k < 16; k++) {
        float4 a0 = *(const float4*)&As[k][ty * 8];
        float4 a1 = *(const float4*)&As[k][ty * 8 + 4];
        float4 c0 = *(const float4*)&Bs[k][tx * 8];
        float4 c1 = *(const float4*)&Bs[k][tx * 8 + 4];
        float av[8] = {a0.x, a0.y, a0.z, a0.w, a1.x, a1.y, a1.z, a1.w};
        float cv[8] = {c0.x, c0.y, c0.z, c0.w, c1.x, c1.y, c1.z, c1.w};
#pragma unroll
        for (int i = 0; i < 8; i++)
#pragma unroll
            for (int j = 0; j < 8; j++) acc[i][j] += av[i] * cv[j];
    }
    float cb = g_param[b] * LOG_EPS;
#pragma unroll
    for (int i = 0; i < 8; i++) {
        int r = R0 + ty * 8 + i;
        float* orow = out + (b << 20) + (r << 10) + C0 + tx * 8;
        float4 v0, v1;
        v0.x = sigf(acc[i][0] + cb); v0.y = sigf(acc[i][1] + cb);
        v0.z = sigf(acc[i][2] + cb); v0.w = sigf(acc[i][3] + cb);
        v1.x = sigf(acc[i][4] + cb); v1.y = sigf(acc[i][5] + cb);
        v1.z = sigf(acc[i][6] + cb); v1.w = sigf(acc[i][7] + cb);
        *(float4*)orow = v0;
        *(float4*)(orow + 4) = v1;
    }
}

// fixup + restore fused: atomicExch claims the adj entry (winner gets the full
// accumulated weight, duplicates get 0 and skip), leaving g_adj zeroed.
__global__ void k_fixres(float* __restrict__ out) {
    int e = blockIdx.x * blockDim.x + threadIdx.x;
    int2 sd = g_edge[e];
    int idx = (sd.x << 10) + (sd.y & 1023);
    float adjv = atomicExch(&g_adj[idx], 0.f);
    if (adjv != 0.f) {
        const float4* A = (const float4*)&g_out[sd.x * 16];
        const float4* C = (const float4*)&g_out[sd.y * 16];
        float g = 0.f;
#pragma unroll
        for (int q = 0; q < 4; q++) {
            float4 a = A[q], c = C[q];
            g += a.x * c.x + a.y * c.y + a.z * c.z + a.w * c.w;
        }
        float p = g_param[sd.x >> 10];
        out[idx] = sigf(g + logf(adjv + 1e-10f) * p);
    }
}

extern "C" void kernel_launch(void* const* d_in, const int* in_sizes, int n_in,
                              void* d_out, int out_size) {
    const float* x      = (const float*)d_in[0];
    const int*   ei32   = (const int*)d_in[1];   // width auto-detected
    const float* ea     = (const float*)d_in[2];
    // d_in[3] = batch (unused; graph id derivable from node id)
    const float* W11    = (const float*)d_in[4];
    const float* b11    = (const float*)d_in[5];
    const float* W21    = (const float*)d_in[6];
    const float* b21    = (const float*)d_in[7];
    const float* Wrel1  = (const float*)d_in[8];
    const float* brel1  = (const float*)d_in[9];
    const float* Wroot1 = (const float*)d_in[10];
    const float* Wrel2  = (const float*)d_in[11];
    const float* brel2  = (const float*)d_in[12];
    const float* Wroot2 = (const float*)d_in[13];
    float* out = (float*)d_out;

    int write_param = (out_size >= CONN + BB) ? 1 : 0;

    k_cvt<<<EE / 256, 256>>>(ei32);
    k_h0<<<NN + 1, 256>>>(x, W21, b21, W11, b11, out + CONN, write_param);
    k_edge1<<<EE / 256, 256>>>(ea);
    k_h1<<<NT / 256, 256>>>(Wrel1, brel1, Wroot1);
    k_edge2<<<EE / 256, 256>>>(ea);
    k_out<<<NT / 128, 128>>>(Wrel2, brel2, Wroot2);
    k_conn<<<dim3(8, 8, 16), 256>>>(out);
    k_fixres<<<EE / 256, 256>>>(out);
}

// round 7
// speedup vs baseline: 1.1965x; 1.0924x over previous
#include <cuda_runtime.h>

#define BB 16
#define NN 1024
#define FF 256
#define NT 16384
#define EE 524288
#define CONN 16777216
#define LOG_EPS -23.025850929940457f

// ---- scratch (device globals: allocation-free; zero at load, every launch
// ---- leaves them zeroed again so graph replays are deterministic) ----
__device__ int2   g_edge[EE];
__device__ float  g_param[BB];
__device__ float  g_h0[NT];
__device__ float2 g_ad1[NT];      // (agg1, deg); zeroed in k_out after consumption
__device__ float  g_agg2[NT * 8]; // zeroed in k_out after consumption
__device__ float  g_out[NT * 16];
__device__ float  g_adj[CONN];    // touched entries zeroed by atomicExch in k_fixres

__device__ __forceinline__ float leaky(float v) { return v >= 0.f ? v : 0.01f * v; }
__device__ __forceinline__ float sigf(float t) {
    return __fdividef(1.f, 1.f + __expf(-t));
}
__device__ __forceinline__ float wred(float v) {
#pragma unroll
    for (int o = 16; o; o >>= 1) v += __shfl_down_sync(0xffffffffu, v, o);
    return v;
}

// ===== A: edge cvt + h0 + param =====
// blocks 0..1023: h0 for n = blk; block 1024: param. All blocks: edge cvt.
#define NTHA (1025 * 256)
__global__ void k_A(const float* __restrict__ x, const int* __restrict__ ei32,
                    const float* __restrict__ W21, const float* __restrict__ b21,
                    const float* __restrict__ W11, const float* __restrict__ b11,
                    float* __restrict__ outp, int write_param) {
    __shared__ float ws[FF];
    const int tid = threadIdx.x, blk = blockIdx.x;
    const int w = tid >> 5, lane = tid & 31;
    // edge width probe: int64 => odd words (high halves) of first 8 vals are 0;
    // int32 => odd words are random node ids, all-zero w.p. 2^-112.
    unsigned probe = (unsigned)ei32[1] | (unsigned)ei32[3] | (unsigned)ei32[5] |
                     (unsigned)ei32[7] | (unsigned)ei32[9] | (unsigned)ei32[11] |
                     (unsigned)ei32[13] | (unsigned)ei32[15];
    bool is64 = (probe == 0u);
    for (int e = blk * 256 + tid; e < EE; e += NTHA) {
        int s, d;
        if (is64) { s = ei32[2 * e]; d = ei32[2 * (EE + e)]; }
        else      { s = ei32[e];     d = ei32[EE + e]; }
        g_edge[e] = make_int2(s, d);
    }
    if (blk < NN) {
        int n = blk;
        ws[tid] = W21[n * FF + tid];
        __syncthreads();
        float bn = b21[n];
#pragma unroll
        for (int rep = 0; rep < 2; rep++) {
            int b = w + rep * 8;
            float s = 0.f;
            for (int f = lane; f < FF; f += 32) s += x[b * FF + f] * ws[f];
            s = wred(s);
            if (lane == 0) g_h0[b * NN + n] = leaky(s + bn);
        }
    } else {
#pragma unroll
        for (int rep = 0; rep < 2; rep++) {
            int b = w + rep * 8;
            float s = 0.f;
            for (int f = lane; f < FF; f += 32) s += x[b * FF + f] * W11[f];
            s = wred(s);
            if (lane == 0) {
                float p = fmaxf(s + b11[0], 0.f);
                g_param[b] = p;
                if (write_param) outp[b] = p;
            }
        }
    }
}

// ===== B: edge1 — (agg1,deg) via one v2 RED + sparse adj accumulation =====
__global__ void k_B(const float* __restrict__ ea) {
    int e = blockIdx.x * blockDim.x + threadIdx.x;
    int2 sd = g_edge[e];
    float wv = ea[e];
    float m = wv * g_h0[sd.x];
    float* dst = (float*)&g_ad1[sd.y];
    asm volatile("red.global.add.v2.f32 [%0], {%1,%2};" ::"l"(dst),
                 "f"(m), "f"(1.f) : "memory");
    atomicAdd(&g_adj[(sd.x << 10) + (sd.y & 1023)], wv);  // (b<<20 | n<<10 | m)
}

// ===== D: edge2 — h1[src] recomputed inline, 8 channels via two v4 REDs =====
__global__ void k_D(const float* __restrict__ ea, const float* __restrict__ Wr1,
                    const float* __restrict__ br1, const float* __restrict__ Wo1) {
    __shared__ float sW[8], sb[8], sR[8];
    if (threadIdx.x < 8) {
        sW[threadIdx.x] = Wr1[threadIdx.x];
        sb[threadIdx.x] = br1[threadIdx.x];
        sR[threadIdx.x] = Wo1[threadIdx.x];
    }
    __syncthreads();
    int e = blockIdx.x * blockDim.x + threadIdx.x;
    int2 sd = g_edge[e];
    float wv = ea[e];
    float2 ad = g_ad1[sd.x];
    float a = ad.x / fmaxf(ad.y, 1.f);
    float h = g_h0[sd.x];
    float v[8];
#pragma unroll
    for (int c = 0; c < 8; c++) v[c] = wv * leaky(a * sW[c] + sb[c] + h * sR[c]);
    float* dst = &g_agg2[sd.y * 8];
    asm volatile("red.global.add.v4.f32 [%0], {%1,%2,%3,%4};" ::"l"(dst),
                 "f"(v[0]), "f"(v[1]), "f"(v[2]), "f"(v[3]) : "memory");
    asm volatile("red.global.add.v4.f32 [%0], {%1,%2,%3,%4};" ::"l"(dst + 4),
                 "f"(v[4]), "f"(v[5]), "f"(v[6]), "f"(v[7]) : "memory");
}

// ===== E: out — h1[i] recomputed inline; restores ad1 and agg2 =====
__global__ void k_E(const float* __restrict__ Wr2, const float* __restrict__ br2,
                    const float* __restrict__ Wo2, const float* __restrict__ Wr1,
                    const float* __restrict__ br1, const float* __restrict__ Wo1) {
    __shared__ float sW[128], sR[128], sb[16], s1[24];
    int t = threadIdx.x;
    if (t < 128) { sW[t] = Wr2[t]; sR[t] = Wo2[t]; }
    if (t < 16) sb[t] = br2[t];
    if (t < 8) { s1[t] = Wr1[t]; s1[8 + t] = br1[t]; s1[16 + t] = Wo1[t]; }
    __syncthreads();
    int i = blockIdx.x * blockDim.x + t;
    float2 ad = g_ad1[i];
    g_ad1[i] = make_float2(0.f, 0.f);          // restore
    float dmax = fmaxf(ad.y, 1.f);
    float a1 = ad.x / dmax;
    float dinv = __fdividef(1.f, dmax);
    float h0 = g_h0[i];
    float h[8];
#pragma unroll
    for (int c = 0; c < 8; c++) h[c] = leaky(a1 * s1[c] + s1[8 + c] + h0 * s1[16 + c]);
    float4* ap = (float4*)&g_agg2[i * 8];
    float4 a0 = ap[0], a1v = ap[1];
    ap[0] = make_float4(0.f, 0.f, 0.f, 0.f);   // restore
    ap[1] = make_float4(0.f, 0.f, 0.f, 0.f);
    float a[8] = {a0.x * dinv, a0.y * dinv, a0.z * dinv, a0.w * dinv,
                  a1v.x * dinv, a1v.y * dinv, a1v.z * dinv, a1v.w * dinv};
    float v[16];
#pragma unroll
    for (int k = 0; k < 16; k++) {
        float s = sb[k];
#pragma unroll
        for (int c = 0; c < 8; c++) s += a[c] * sW[k * 8 + c] + h[c] * sR[k * 8 + c];
        v[k] = leaky(s);
    }
    float4* o = (float4*)&g_out[i * 16];
#pragma unroll
    for (int q = 0; q < 4; q++)
        o[q] = make_float4(v[q * 4], v[q * 4 + 1], v[q * 4 + 2], v[q * 4 + 3]);
}

// ===== F: conn = sigmoid(gram + param*log(eps)) assuming adj=0 =====
__global__ void k_F(float* __restrict__ out) {
    __shared__ float As[16][132];
    __shared__ float Bs[16][132];
    int b = blockIdx.z;
    int R0 = blockIdx.y << 7, C0 = blockIdx.x << 7;
    const float* ob = g_out + b * NN * 16;
    int tid = threadIdx.x;
#pragma unroll
    for (int it = 0; it < 2; it++) {
        int v = tid + it * 256;            // 512 float4s cover both 128x16 tiles
        int r = v >> 2, q = (v & 3) << 2;
        float4 a = *(const float4*)(ob + (R0 + r) * 16 + q);
        As[q + 0][r] = a.x; As[q + 1][r] = a.y; As[q + 2][r] = a.z; As[q + 3][r] = a.w;
        float4 c = *(const float4*)(ob + (C0 + r) * 16 + q);
        Bs[q + 0][r] = c.x; Bs[q + 1][r] = c.y; Bs[q + 2][r] = c.z; Bs[q + 3][r] = c.w;
    }
    __syncthreads();
    int tx = tid & 15, ty = tid >> 4;
    float acc[8][8];
#pragma unroll
    for (int i = 0; i < 8; i++)
#pragma unroll
        for (int j = 0; j < 8; j++) acc[i][j] = 0.f;
#pragma unroll
    for (int k = 0; k < 16; k++) {
        float4 a0 = *(const float4*)&As[k][ty * 8];
        float4 a1 = *(const float4*)&As[k][ty * 8 + 4];
        float4 c0 = *(const float4*)&Bs[k][tx * 8];
        float4 c1 = *(const float4*)&Bs[k][tx * 8 + 4];
        float av[8] = {a0.x, a0.y, a0.z, a0.w, a1.x, a1.y, a1.z, a1.w};
        float cv[8] = {c0.x, c0.y, c0.z, c0.w, c1.x, c1.y, c1.z, c1.w};
#pragma unroll
        for (int i = 0; i < 8; i++)
#pragma unroll
            for (int j = 0; j < 8; j++) acc[i][j] += av[i] * cv[j];
    }
    float cb = g_param[b] * LOG_EPS;
#pragma unroll
    for (int i = 0; i < 8; i++) {
        int r = R0 + ty * 8 + i;
        float* orow = out + (b << 20) + (r << 10) + C0 + tx * 8;
        float4 v0, v1;
        v0.x = sigf(acc[i][0] + cb); v0.y = sigf(acc[i][1] + cb);
        v0.z = sigf(acc[i][2] + cb); v0.w = sigf(acc[i][3] + cb);
        v1.x = sigf(acc[i][4] + cb); v1.y = sigf(acc[i][5] + cb);
        v1.z = sigf(acc[i][6] + cb); v1.w = sigf(acc[i][7] + cb);
        *(float4*)orow = v0;
        *(float4*)(orow + 4) = v1;
    }
}

// ===== G: fixup + restore fused; atomicExch claims (dedups) and zeroes adj =====
__global__ void k_G(float* __restrict__ out) {
    int e = blockIdx.x * blockDim.x + threadIdx.x;
    int2 sd = g_edge[e];
    int idx = (sd.x << 10) + (sd.y & 1023);
    float adjv = atomicExch(&g_adj[idx], 0.f);
    if (adjv != 0.f) {
        const float4* A = (const float4*)&g_out[sd.x * 16];
        const float4* C = (const float4*)&g_out[sd.y * 16];
        float g = 0.f;
#pragma unroll
        for (int q = 0; q < 4; q++) {
            float4 a = A[q], c = C[q];
            g += a.x * c.x + a.y * c.y + a.z * c.z + a.w * c.w;
        }
        float p = g_param[sd.x >> 10];
        out[idx] = sigf(g + logf(adjv + 1e-10f) * p);
    }
}

extern "C" void kernel_launch(void* const* d_in, const int* in_sizes, int n_in,
                              void* d_out, int out_size) {
    const float* x      = (const float*)d_in[0];
    const int*   ei32   = (const int*)d_in[1];   // width auto-detected in-kernel
    const float* ea     = (const float*)d_in[2];
    // d_in[3] = batch (unused; graph id derivable from node id)
    const float* W11    = (const float*)d_in[4];
    const float* b11    = (const float*)d_in[5];
    const float* W21    = (const float*)d_in[6];
    const float* b21    = (const float*)d_in[7];
    const float* Wrel1  = (const float*)d_in[8];
    const float* brel1  = (const float*)d_in[9];
    const float* Wroot1 = (const float*)d_in[10];
    const float* Wrel2  = (const float*)d_in[11];
    const float* brel2  = (const float*)d_in[12];
    const float* Wroot2 = (const float*)d_in[13];
    float* out = (float*)d_out;

    int write_param = (out_size >= CONN + BB) ? 1 : 0;

    k_A<<<NN + 1, 256>>>(x, ei32, W21, b21, W11, b11, out + CONN, write_param);
    k_B<<<EE / 256, 256>>>(ea);
    k_D<<<EE / 256, 256>>>(ea, Wrel1, brel1, Wroot1);
    k_E<<<NT / 128, 128>>>(Wrel2, brel2, Wroot2, Wrel1, brel1, Wroot1);
    k_F<<<dim3(8, 8, 16), 256>>>(out);
    k_G<<<EE / 256, 256>>>(out);
}

// round 8
// speedup vs baseline: 1.2093x; 1.0107x over previous
#include <cuda_runtime.h>

#define BB 16
#define NN 1024
#define FF 256
#define NT 16384
#define EE 524288
#define CONN 16777216
#define LOG_EPS -23.025850929940457f

// ---- scratch (device globals: allocation-free; zero at load, every launch
// ---- leaves them zeroed again so graph replays are deterministic) ----
__device__ int2   g_edge[EE];
__device__ float  g_param[BB];
__device__ float  g_h0[NT];
__device__ float2 g_ad1[NT];      // (agg1, deg); zeroed in k_E after consumption
__device__ float  g_agg2[NT * 8]; // zeroed in k_E after consumption
__device__ float  g_out[NT * 16];
__device__ float  g_adj[CONN];    // touched entries zeroed by atomicExch in k_G

__device__ __forceinline__ float leaky(float v) { return v >= 0.f ? v : 0.01f * v; }
__device__ __forceinline__ float sigf(float t) {
    return __fdividef(1.f, 1.f + __expf(-t));
}
__device__ __forceinline__ float wred(float v) {
#pragma unroll
    for (int o = 16; o; o >>= 1) v += __shfl_down_sync(0xffffffffu, v, o);
    return v;
}

// ===== A: edge cvt + h0 + param =====
#define NTHA (1025 * 256)
__global__ void k_A(const float* __restrict__ x, const int* __restrict__ ei32,
                    const float* __restrict__ W21, const float* __restrict__ b21,
                    const float* __restrict__ W11, const float* __restrict__ b11,
                    float* __restrict__ outp, int write_param) {
    __shared__ float ws[FF];
    const int tid = threadIdx.x, blk = blockIdx.x;
    const int w = tid >> 5, lane = tid & 31;
    // width probe: int64 => odd words (high halves) of first 8 vals are all 0
    unsigned probe = (unsigned)ei32[1] | (unsigned)ei32[3] | (unsigned)ei32[5] |
                     (unsigned)ei32[7] | (unsigned)ei32[9] | (unsigned)ei32[11] |
                     (unsigned)ei32[13] | (unsigned)ei32[15];
    bool is64 = (probe == 0u);
    for (int e = blk * 256 + tid; e < EE; e += NTHA) {
        int s, d;
        if (is64) { s = ei32[2 * e]; d = ei32[2 * (EE + e)]; }
        else      { s = ei32[e];     d = ei32[EE + e]; }
        g_edge[e] = make_int2(s, d);
    }
    if (blk < NN) {
        int n = blk;
        ws[tid] = W21[n * FF + tid];
        __syncthreads();
        float bn = b21[n];
#pragma unroll
        for (int rep = 0; rep < 2; rep++) {
            int b = w + rep * 8;
            float s = 0.f;
            for (int f = lane; f < FF; f += 32) s += x[b * FF + f] * ws[f];
            s = wred(s);
            if (lane == 0) g_h0[b * NN + n] = leaky(s + bn);
        }
    } else {
#pragma unroll
        for (int rep = 0; rep < 2; rep++) {
            int b = w + rep * 8;
            float s = 0.f;
            for (int f = lane; f < FF; f += 32) s += x[b * FF + f] * W11[f];
            s = wred(s);
            if (lane == 0) {
                float p = fmaxf(s + b11[0], 0.f);
                g_param[b] = p;
                if (write_param) outp[b] = p;
            }
        }
    }
}

// ===== B: edge1 — (agg1,deg) one v2 RED + sparse adj accumulation =====
__global__ void k_B(const float* __restrict__ ea) {
    cudaTriggerProgrammaticLaunchCompletion();
    int e = blockIdx.x * blockDim.x + threadIdx.x;
    float wv = ea[e];                    // independent of k_A output
    cudaGridDependencySynchronize();
    int2 sd = g_edge[e];
    float m = wv * g_h0[sd.x];
    float* dst = (float*)&g_ad1[sd.y];
    asm volatile("red.global.add.v2.f32 [%0], {%1,%2};" ::"l"(dst),
                 "f"(m), "f"(1.f) : "memory");
    atomicAdd(&g_adj[(sd.x << 10) + (sd.y & 1023)], wv);  // (b<<20 | n<<10 | m)
}

// ===== D: edge2 — h1[src] recomputed inline, two v4 REDs =====
__global__ void k_D(const float* __restrict__ ea, const float* __restrict__ Wr1,
                    const float* __restrict__ br1, const float* __restrict__ Wo1) {
    cudaTriggerProgrammaticLaunchCompletion();
    __shared__ float sW[8], sb[8], sR[8];
    if (threadIdx.x < 8) {
        sW[threadIdx.x] = Wr1[threadIdx.x];
        sb[threadIdx.x] = br1[threadIdx.x];
        sR[threadIdx.x] = Wo1[threadIdx.x];
    }
    int e = blockIdx.x * blockDim.x + threadIdx.x;
    float wv = ea[e];
    __syncthreads();
    cudaGridDependencySynchronize();
    int2 sd = g_edge[e];
    float2 ad = g_ad1[sd.x];
    float a = ad.x / fmaxf(ad.y, 1.f);
    float h = g_h0[sd.x];
    float v[8];
#pragma unroll
    for (int c = 0; c < 8; c++) v[c] = wv * leaky(a * sW[c] + sb[c] + h * sR[c]);
    float* dst = &g_agg2[sd.y * 8];
    asm volatile("red.global.add.v4.f32 [%0], {%1,%2,%3,%4};" ::"l"(dst),
                 "f"(v[0]), "f"(v[1]), "f"(v[2]), "f"(v[3]) : "memory");
    asm volatile("red.global.add.v4.f32 [%0], {%1,%2,%3,%4};" ::"l"(dst + 4),
                 "f"(v[4]), "f"(v[5]), "f"(v[6]), "f"(v[7]) : "memory");
}

// ===== E: out — thread per (node, channel-quad); restores ad1, agg2 =====
// 4 threads of one node are adjacent lanes in one warp: their loads of
// ad1/agg2 precede the q-owned restore stores in warp program order.
__global__ void k_E(const float* __restrict__ Wr2, const float* __restrict__ br2,
                    const float* __restrict__ Wo2, const float* __restrict__ Wr1,
                    const float* __restrict__ br1, const float* __restrict__ Wo1) {
    cudaTriggerProgrammaticLaunchCompletion();
    __shared__ float sW[128], sR[128], sb[16], s1[24];
    int t = threadIdx.x;
    if (t < 128) { sW[t] = Wr2[t]; sR[t] = Wo2[t]; }
    if (t < 16) sb[t] = br2[t];
    if (t < 8) { s1[t] = Wr1[t]; s1[8 + t] = br1[t]; s1[16 + t] = Wo1[t]; }
    __syncthreads();
    cudaGridDependencySynchronize();
    int gt = blockIdx.x * blockDim.x + t;      // 0 .. 4*NT-1
    int i = gt >> 2, q = gt & 3;
    float2 ad = g_ad1[i];
    float4* ap = (float4*)&g_agg2[i * 8];
    float4 a0 = ap[0], a1v = ap[1];
    float h0 = g_h0[i];
    if (q == 0) g_ad1[i] = make_float2(0.f, 0.f);            // restore
    if (q == 1) ap[0] = make_float4(0.f, 0.f, 0.f, 0.f);     // restore
    if (q == 2) ap[1] = make_float4(0.f, 0.f, 0.f, 0.f);     // restore
    float dmax = fmaxf(ad.y, 1.f);
    float a1 = ad.x / dmax;
    float dinv = __fdividef(1.f, dmax);
    float h[8];
#pragma unroll
    for (int c = 0; c < 8; c++) h[c] = leaky(a1 * s1[c] + s1[8 + c] + h0 * s1[16 + c]);
    float a[8] = {a0.x * dinv, a0.y * dinv, a0.z * dinv, a0.w * dinv,
                  a1v.x * dinv, a1v.y * dinv, a1v.z * dinv, a1v.w * dinv};
    float v[4];
#pragma unroll
    for (int kk = 0; kk < 4; kk++) {
        int k = q * 4 + kk;
        float s = sb[k];
#pragma unroll
        for (int c = 0; c < 8; c++) s += a[c] * sW[k * 8 + c] + h[c] * sR[k * 8 + c];
        v[kk] = leaky(s);
    }
    *(float4*)&g_out[i * 16 + q * 4] = make_float4(v[0], v[1], v[2], v[3]);
}

// ===== F: conn = sigmoid(gram + param*log(eps)) assuming adj=0 =====
__global__ void k_F(float* __restrict__ out) {
    cudaTriggerProgrammaticLaunchCompletion();
    __shared__ float As[16][132];
    __shared__ float Bs[16][132];
    int b = blockIdx.z;
    int R0 = blockIdx.y << 7, C0 = blockIdx.x << 7;
    const float* ob = g_out + b * NN * 16;
    int tid = threadIdx.x;
    cudaGridDependencySynchronize();
#pragma unroll
    for (int it = 0; it < 2; it++) {
        int v = tid + it * 256;            // 512 float4s cover both 128x16 tiles
        int r = v >> 2, q = (v & 3) << 2;
        float4 a = *(const float4*)(ob + (R0 + r) * 16 + q);
        As[q + 0][r] = a.x; As[q + 1][r] = a.y; As[q + 2][r] = a.z; As[q + 3][r] = a.w;
        float4 c = *(const float4*)(ob + (C0 + r) * 16 + q);
        Bs[q + 0][r] = c.x; Bs[q + 1][r] = c.y; Bs[q + 2][r] = c.z; Bs[q + 3][r] = c.w;
    }
    __syncthreads();
    int tx = tid & 15, ty = tid >> 4;
    float acc[8][8];
#pragma unroll
    for (int i = 0; i < 8; i++)
#pragma unroll
        for (int j = 0; j < 8; j++) acc[i][j] = 0.f;
#pragma unroll
    for (int k = 0; k < 16; k++) {
        float4 a0 = *(const float4*)&As[k][ty * 8];
        float4 a1 = *(const float4*)&As[k][ty * 8 + 4];
        float4 c0 = *(const float4*)&Bs[k][tx * 8];
        float4 c1 = *(const float4*)&Bs[k][tx * 8 + 4];
        float av[8] = {a0.x, a0.y, a0.z, a0.w, a1.x, a1.y, a1.z, a1.w};
        float cv[8] = {c0.x, c0.y, c0.z, c0.w, c1.x, c1.y, c1.z, c1.w};
#pragma unroll
        for (int i = 0; i < 8; i++)
#pragma unroll
            for (int j = 0; j < 8; j++) acc[i][j] += av[i] * cv[j];
    }
    float cb = g_param[b] * LOG_EPS;
#pragma unroll
    for (int i = 0; i < 8; i++) {
        int r = R0 + ty * 8 + i;
        float* orow = out + (b << 20) + (r << 10) + C0 + tx * 8;
        float4 v0, v1;
        v0.x = sigf(acc[i][0] + cb); v0.y = sigf(acc[i][1] + cb);
        v0.z = sigf(acc[i][2] + cb); v0.w = sigf(acc[i][3] + cb);
        v1.x = sigf(acc[i][4] + cb); v1.y = sigf(acc[i][5] + cb);
        v1.z = sigf(acc[i][6] + cb); v1.w = sigf(acc[i][7] + cb);
        *(float4*)orow = v0;
        *(float4*)(orow + 4) = v1;
    }
}

// ===== G: fixup + restore fused; atomicExch claims (dedups) and zeroes adj =====
__global__ void k_G(float* __restrict__ out) {
    cudaTriggerProgrammaticLaunchCompletion();
    int e = blockIdx.x * blockDim.x + threadIdx.x;
    cudaGridDependencySynchronize();
    int2 sd = g_edge[e];
    int idx = (sd.x << 10) + (sd.y & 1023);
    float adjv = atomicExch(&g_adj[idx], 0.f);
    if (adjv != 0.f) {
        const float4* A = (const float4*)&g_out[sd.x * 16];
        const float4* C = (const float4*)&g_out[sd.y * 16];
        float g = 0.f;
#pragma unroll
        for (int q = 0; q < 4; q++) {
            float4 a = A[q], c = C[q];
            g += a.x * c.x + a.y * c.y + a.z * c.z + a.w * c.w;
        }
        float p = g_param[sd.x >> 10];
        out[idx] = sigf(g + logf(adjv + 1e-10f) * p);
    }
}

template <typename F, typename... Args>
static void launch_pdl(F fn, dim3 grid, dim3 block, Args... args) {
    cudaLaunchConfig_t cfg = {};
    cfg.gridDim = grid;
    cfg.blockDim = block;
    cfg.dynamicSmemBytes = 0;
    cfg.stream = 0;                      // legacy default stream (same as <<<>>>)
    cudaLaunchAttribute at[1];
    at[0].id = cudaLaunchAttributeProgrammaticStreamSerialization;
    at[0].val.programmaticStreamSerializationAllowed = 1;
    cfg.attrs = at;
    cfg.numAttrs = 1;
    cudaLaunchKernelEx(&cfg, fn, args...);
}

extern "C" void kernel_launch(void* const* d_in, const int* in_sizes, int n_in,
                              void* d_out, int out_size) {
    const float* x      = (const float*)d_in[0];
    const int*   ei32   = (const int*)d_in[1];   // width auto-detected in-kernel
    const float* ea     = (const float*)d_in[2];
    // d_in[3] = batch (unused; graph id derivable from node id)
    const float* W11    = (const float*)d_in[4];
    const float* b11    = (const float*)d_in[5];
    const float* W21    = (const float*)d_in[6];
    const float* b21    = (const float*)d_in[7];
    const float* Wrel1  = (const float*)d_in[8];
    const float* brel1  = (const float*)d_in[9];
    const float* Wroot1 = (const float*)d_in[10];
    const float* Wrel2  = (const float*)d_in[11];
    const float* brel2  = (const float*)d_in[12];
    const float* Wroot2 = (const float*)d_in[13];
    float* out = (float*)d_out;

    int write_param = (out_size >= CONN + BB) ? 1 : 0;

    k_A<<<NN + 1, 256>>>(x, ei32, W21, b21, W11, b11, out + CONN, write_param);
    launch_pdl(k_B, dim3(EE / 256), dim3(256), ea);
    launch_pdl(k_D, dim3(EE / 256), dim3(256), ea, Wrel1, brel1, Wroot1);
    launch_pdl(k_E, dim3(NT / 64), dim3(256), Wrel2, brel2, Wroot2, Wrel1, brel1, Wroot1);
    launch_pdl(k_F, dim3(8, 8, 16), dim3(256), out);
    launch_pdl(k_G, dim3(EE / 256), dim3(256), out);
}

// round 9
// speedup vs baseline: 1.2658x; 1.0467x over previous
#include <cuda_runtime.h>

#define BB 16
#define NN 1024
#define FF 256
#define NT 16384
#define EE 524288
#define CONN 16777216
#define LOG_EPS -23.025850929940457f

// ---- scratch (device globals: allocation-free; zero at load, every launch
// ---- leaves them zeroed again so graph replays are deterministic) ----
__device__ int2   g_edge[EE];
__device__ float  g_param[BB];
__device__ float  g_h0[NT];
__device__ float2 g_ad1[NT];      // (agg1, deg); zeroed in k_E after consumption
__device__ float  g_agg2[NT * 8]; // zeroed in k_E after consumption
__device__ float  g_out[NT * 16];
__device__ float  g_adj[CONN];    // touched entries zeroed by plain store in k_G

__device__ __forceinline__ float leaky(float v) { return v >= 0.f ? v : 0.01f * v; }
__device__ __forceinline__ float sigf(float t) {
    return __fdividef(1.f, 1.f + __expf(-t));
}
__device__ __forceinline__ float wred(float v) {
#pragma unroll
    for (int o = 16; o; o >>= 1) v += __shfl_down_sync(0xffffffffu, v, o);
    return v;
}

#define FMA2(acc, a2, b2) \
    asm("fma.rn.f32x2 %0, %1, %2, %0;" : "+l"(acc) : "l"(a2), "l"(b2))
#define PACKDUP(d, f) \
    asm("mov.b64 %0, {%1, %1};" : "=l"(d) : "r"(__float_as_uint(f)))

// ===== A: edge cvt + h0 + param =====
#define NTHA (1025 * 256)
__global__ void k_A(const float* __restrict__ x, const int* __restrict__ ei32,
                    const float* __restrict__ W21, const float* __restrict__ b21,
                    const float* __restrict__ W11, const float* __restrict__ b11,
                    float* __restrict__ outp, int write_param) {
    __shared__ float ws[FF];
    const int tid = threadIdx.x, blk = blockIdx.x;
    const int w = tid >> 5, lane = tid & 31;
    // width probe: int64 => odd words (high halves) of first 8 vals are all 0
    unsigned probe = (unsigned)ei32[1] | (unsigned)ei32[3] | (unsigned)ei32[5] |
                     (unsigned)ei32[7] | (unsigned)ei32[9] | (unsigned)ei32[11] |
                     (unsigned)ei32[13] | (unsigned)ei32[15];
    bool is64 = (probe == 0u);
    for (int e = blk * 256 + tid; e < EE; e += NTHA) {
        int s, d;
        if (is64) { s = ei32[2 * e]; d = ei32[2 * (EE + e)]; }
        else      { s = ei32[e];     d = ei32[EE + e]; }
        g_edge[e] = make_int2(s, d);
    }
    if (blk < NN) {
        int n = blk;
        ws[tid] = W21[n * FF + tid];
        __syncthreads();
        float bn = b21[n];
#pragma unroll
        for (int rep = 0; rep < 2; rep++) {
            int b = w + rep * 8;
            float s = 0.f;
            for (int f = lane; f < FF; f += 32) s += x[b * FF + f] * ws[f];
            s = wred(s);
            if (lane == 0) g_h0[b * NN + n] = leaky(s + bn);
        }
    } else {
#pragma unroll
        for (int rep = 0; rep < 2; rep++) {
            int b = w + rep * 8;
            float s = 0.f;
            for (int f = lane; f < FF; f += 32) s += x[b * FF + f] * W11[f];
            s = wred(s);
            if (lane == 0) {
                float p = fmaxf(s + b11[0], 0.f);
                g_param[b] = p;
                if (write_param) outp[b] = p;
            }
        }
    }
}

// ===== B: edge1 — 2 edges/thread; (agg1,deg) v2 RED + adj atomic =====
__global__ void k_B(const float* __restrict__ ea) {
    cudaTriggerProgrammaticLaunchCompletion();
    int t = blockIdx.x * blockDim.x + threadIdx.x;     // 0 .. EE/2-1
    float2 wv = ((const float2*)ea)[t];                // independent of k_A
    cudaGridDependencySynchronize();
    int4 e2 = ((const int4*)g_edge)[t];                // (s0,d0,s1,d1)
#pragma unroll
    for (int k = 0; k < 2; k++) {
        int s = k ? e2.z : e2.x, d = k ? e2.w : e2.y;
        float w = k ? wv.y : wv.x;
        float m = w * g_h0[s];
        float* dst = (float*)&g_ad1[d];
        asm volatile("red.global.add.v2.f32 [%0], {%1,%2};" ::"l"(dst),
                     "f"(m), "f"(1.f) : "memory");
        atomicAdd(&g_adj[(s << 10) + (d & 1023)], w);  // (b<<20 | n<<10 | m)
    }
}

// ===== D: edge2 — 2 edges/thread; h1[src] inline; two v4 REDs per edge =====
__global__ void k_D(const float* __restrict__ ea, const float* __restrict__ Wr1,
                    const float* __restrict__ br1, const float* __restrict__ Wo1) {
    cudaTriggerProgrammaticLaunchCompletion();
    __shared__ float sW[8], sb[8], sR[8];
    if (threadIdx.x < 8) {
        sW[threadIdx.x] = Wr1[threadIdx.x];
        sb[threadIdx.x] = br1[threadIdx.x];
        sR[threadIdx.x] = Wo1[threadIdx.x];
    }
    int t = blockIdx.x * blockDim.x + threadIdx.x;
    float2 wv = ((const float2*)ea)[t];
    __syncthreads();
    cudaGridDependencySynchronize();
    int4 e2 = ((const int4*)g_edge)[t];
#pragma unroll
    for (int k = 0; k < 2; k++) {
        int s = k ? e2.z : e2.x, d = k ? e2.w : e2.y;
        float w = k ? wv.y : wv.x;
        float2 ad = g_ad1[s];
        float a = ad.x / fmaxf(ad.y, 1.f);
        float h = g_h0[s];
        float v[8];
#pragma unroll
        for (int c = 0; c < 8; c++) v[c] = w * leaky(a * sW[c] + sb[c] + h * sR[c]);
        float* dst = &g_agg2[d * 8];
        asm volatile("red.global.add.v4.f32 [%0], {%1,%2,%3,%4};" ::"l"(dst),
                     "f"(v[0]), "f"(v[1]), "f"(v[2]), "f"(v[3]) : "memory");
        asm volatile("red.global.add.v4.f32 [%0], {%1,%2,%3,%4};" ::"l"(dst + 4),
                     "f"(v[4]), "f"(v[5]), "f"(v[6]), "f"(v[7]) : "memory");
    }
}

// ===== E: out — thread per (node, channel-quad); restores ad1, agg2 =====
__global__ void k_E(const float* __restrict__ Wr2, const float* __restrict__ br2,
                    const float* __restrict__ Wo2, const float* __restrict__ Wr1,
                    const float* __restrict__ br1, const float* __restrict__ Wo1) {
    cudaTriggerProgrammaticLaunchCompletion();
    __shared__ float sW[128], sR[128], sb[16], s1[24];
    int t = threadIdx.x;
    if (t < 128) { sW[t] = Wr2[t]; sR[t] = Wo2[t]; }
    if (t < 16) sb[t] = br2[t];
    if (t < 8) { s1[t] = Wr1[t]; s1[8 + t] = br1[t]; s1[16 + t] = Wo1[t]; }
    __syncthreads();
    cudaGridDependencySynchronize();
    int gt = blockIdx.x * blockDim.x + t;      // 0 .. 4*NT-1
    int i = gt >> 2, q = gt & 3;
    float2 ad = g_ad1[i];
    float4* ap = (float4*)&g_agg2[i * 8];
    float4 a0 = ap[0], a1v = ap[1];
    float h0 = g_h0[i];
    if (q == 0) g_ad1[i] = make_float2(0.f, 0.f);            // restore
    if (q == 1) ap[0] = make_float4(0.f, 0.f, 0.f, 0.f);     // restore
    if (q == 2) ap[1] = make_float4(0.f, 0.f, 0.f, 0.f);     // restore
    float dmax = fmaxf(ad.y, 1.f);
    float a1 = ad.x / dmax;
    float dinv = __fdividef(1.f, dmax);
    float h[8];
#pragma unroll
    for (int c = 0; c < 8; c++) h[c] = leaky(a1 * s1[c] + s1[8 + c] + h0 * s1[16 + c]);
    float a[8] = {a0.x * dinv, a0.y * dinv, a0.z * dinv, a0.w * dinv,
                  a1v.x * dinv, a1v.y * dinv, a1v.z * dinv, a1v.w * dinv};
    float v[4];
#pragma unroll
    for (int kk = 0; kk < 4; kk++) {
        int k = q * 4 + kk;
        float s = sb[k];
#pragma unroll
        for (int c = 0; c < 8; c++) s += a[c] * sW[k * 8 + c] + h[c] * sR[k * 8 + c];
        v[kk] = leaky(s);
    }
    *(float4*)&g_out[i * 16 + q * 4] = make_float4(v[0], v[1], v[2], v[3]);
}

// ===== F: conn = sigmoid(gram + param*log(eps)) assuming adj=0; f32x2 FMA =====
__global__ void k_F(float* __restrict__ out) {
    cudaTriggerProgrammaticLaunchCompletion();
    __shared__ __align__(16) float As[16][132];
    __shared__ __align__(16) float Bs[16][132];
    int b = blockIdx.z;
    int R0 = blockIdx.y << 7, C0 = blockIdx.x << 7;
    const float* ob = g_out + b * NN * 16;
    int tid = threadIdx.x;
    cudaGridDependencySynchronize();
#pragma unroll
    for (int it = 0; it < 2; it++) {
        int v = tid + it * 256;            // 512 float4s cover both 128x16 tiles
        int r = v >> 2, q = (v & 3) << 2;
        float4 a = *(const float4*)(ob + (R0 + r) * 16 + q);
        As[q + 0][r] = a.x; As[q + 1][r] = a.y; As[q + 2][r] = a.z; As[q + 3][r] = a.w;
        float4 c = *(const float4*)(ob + (C0 + r) * 16 + q);
        Bs[q + 0][r] = c.x; Bs[q + 1][r] = c.y; Bs[q + 2][r] = c.z; Bs[q + 3][r] = c.w;
    }
    __syncthreads();
    int tx = tid & 15, ty = tid >> 4;
    unsigned long long accp[8][4];
#pragma unroll
    for (int i = 0; i < 8; i++)
#pragma unroll
        for (int j = 0; j < 4; j++) accp[i][j] = 0ull;
#pragma unroll
    for (int k = 0; k < 16; k++) {
        float4 a0 = *(const float4*)&As[k][ty * 8];
        float4 a1 = *(const float4*)&As[k][ty * 8 + 4];
        float av[8] = {a0.x, a0.y, a0.z, a0.w, a1.x, a1.y, a1.z, a1.w};
        unsigned long long av2[8];
#pragma unroll
        for (int i = 0; i < 8; i++) PACKDUP(av2[i], av[i]);
        const unsigned long long* pb = (const unsigned long long*)&Bs[k][tx * 8];
        unsigned long long cv2[4] = {pb[0], pb[1], pb[2], pb[3]};
#pragma unroll
        for (int i = 0; i < 8; i++)
#pragma unroll
            for (int j = 0; j < 4; j++) FMA2(accp[i][j], av2[i], cv2[j]);
    }
    float cb = g_param[b] * LOG_EPS;
#pragma unroll
    for (int i = 0; i < 8; i++) {
        int r = R0 + ty * 8 + i;
        float* orow = out + (b << 20) + (r << 10) + C0 + tx * 8;
        float ac[8];
#pragma unroll
        for (int j = 0; j < 4; j++) {
            unsigned lo, hi;
            asm("mov.b64 {%0, %1}, %2;" : "=r"(lo), "=r"(hi) : "l"(accp[i][j]));
            ac[2 * j] = __uint_as_float(lo);
            ac[2 * j + 1] = __uint_as_float(hi);
        }
        float4 v0, v1;
        v0.x = sigf(ac[0] + cb); v0.y = sigf(ac[1] + cb);
        v0.z = sigf(ac[2] + cb); v0.w = sigf(ac[3] + cb);
        v1.x = sigf(ac[4] + cb); v1.y = sigf(ac[5] + cb);
        v1.z = sigf(ac[6] + cb); v1.w = sigf(ac[7] + cb);
        *(float4*)orow = v0;
        *(float4*)(orow + 4) = v1;
    }
}

// ===== G: fixup + restore, atomic-free; 2 edges/thread =====
// Duplicate edges: all dup threads read the same final adj value (or 0 if a
// sibling already restored) and compute the identical output value, so the
// plain ld/st race is benign; every touched adj entry ends at 0.
__global__ void k_G(float* __restrict__ out) {
    cudaTriggerProgrammaticLaunchCompletion();
    int t = blockIdx.x * blockDim.x + threadIdx.x;
    cudaGridDependencySynchronize();
    int4 e2 = ((const int4*)g_edge)[t];
#pragma unroll
    for (int k = 0; k < 2; k++) {
        int s = k ? e2.z : e2.x, d = k ? e2.w : e2.y;
        int idx = (s << 10) + (d & 1023);
        float adjv = g_adj[idx];
        if (adjv != 0.f) {
            g_adj[idx] = 0.f;                              // restore
            const float4* A = (const float4*)&g_out[s * 16];
            const float4* C = (const float4*)&g_out[d * 16];
            float g = 0.f;
#pragma unroll
            for (int q = 0; q < 4; q++) {
                float4 a = A[q], c = C[q];
                g += a.x * c.x + a.y * c.y + a.z * c.z + a.w * c.w;
            }
            float p = g_param[s >> 10];
            out[idx] = sigf(g + logf(adjv + 1e-10f) * p);
        }
    }
}

template <typename F, typename... Args>
static void launch_pdl(F fn, dim3 grid, dim3 block, Args... args) {
    cudaLaunchConfig_t cfg = {};
    cfg.gridDim = grid;
    cfg.blockDim = block;
    cfg.dynamicSmemBytes = 0;
    cfg.stream = 0;
    cudaLaunchAttribute at[1];
    at[0].id = cudaLaunchAttributeProgrammaticStreamSerialization;
    at[0].val.programmaticStreamSerializationAllowed = 1;
    cfg.attrs = at;
    cfg.numAttrs = 1;
    cudaLaunchKernelEx(&cfg, fn, args...);
}

extern "C" void kernel_launch(void* const* d_in, const int* in_sizes, int n_in,
                              void* d_out, int out_size) {
    const float* x      = (const float*)d_in[0];
    const int*   ei32   = (const int*)d_in[1];   // width auto-detected in-kernel
    const float* ea     = (const float*)d_in[2];
    // d_in[3] = batch (unused; graph id derivable from node id)
    const float* W11    = (const float*)d_in[4];
    const float* b11    = (const float*)d_in[5];
    const float* W21    = (const float*)d_in[6];
    const float* b21    = (const float*)d_in[7];
    const float* Wrel1  = (const float*)d_in[8];
    const float* brel1  = (const float*)d_in[9];
    const float* Wroot1 = (const float*)d_in[10];
    const float* Wrel2  = (const float*)d_in[11];
    const float* brel2  = (const float*)d_in[12];
    const float* Wroot2 = (const float*)d_in[13];
    float* out = (float*)d_out;

    int write_param = (out_size >= CONN + BB) ? 1 : 0;

    k_A<<<NN + 1, 256>>>(x, ei32, W21, b21, W11, b11, out + CONN, write_param);
    launch_pdl(k_B, dim3(EE / 512), dim3(256), ea);
    launch_pdl(k_D, dim3(EE / 512), dim3(256), ea, Wrel1, brel1, Wroot1);
    launch_pdl(k_E, dim3(NT / 64), dim3(256), Wrel2, brel2, Wroot2, Wrel1, brel1, Wroot1);
    launch_pdl(k_F, dim3(8, 8, 16), dim3(256), out);
    launch_pdl(k_G, dim3(EE / 512), dim3(256), out);
}